// round 1
// baseline (speedup 1.0000x reference)
#include <cuda_runtime.h>

#define SLEN   53
#define NPIX   (SLEN * SLEN)   // 2809
#define TPB    256

__global__ void __launch_bounds__(TPB)
lens_decoder_kernel(const float* __restrict__ params,   // [ntiles, 12]
                    const float* __restrict__ bools,    // [ntiles]
                    float* __restrict__ out)            // [ntiles, NPIX]
{
    __shared__ float etab[SLEN];

    const int tile = blockIdx.x;
    const float* p = params + tile * 12;

    // ---- per-tile scalars (redundant per thread; broadcast L1 loads) ----
    const float flux  = p[0] * 1000.0f + 100.0f;
    const float sigma = p[3] * 3.0f + 1.0f;
    const float s2    = sigma * sigma;
    const float b     = p[7];
    const float cx    = p[8];
    const float cy    = p[9];
    const float e1    = p[10];
    const float e2    = p[11];

    const float ell   = sqrtf(e1 * e1 + e2 * e2);
    const float q     = (1.0f - ell) / (1.0f + ell);
    const float phir  = atanf(e2 / e1);
    const float cosp  = cosf(phir);
    const float sinp  = sinf(phir);
    const float invq  = 1.0f / q;
    const float qfact = sqrtf(invq - q);
    const bool  use_t = (qfact >= 0.001f);
    const float safe  = fmaxf(qfact, 0.001f);
    const float bsafe = b / safe;
    const float A     = flux / (6.283185307179586f * s2);
    const float Am    = A * bools[tile];
    const float n2s2  = -0.5f / s2;

    // ---- separable Gaussian table on the integer sampling grid ----
    if (threadIdx.x < SLEN) {
        float d = (float)threadIdx.x - 26.0f;
        etab[threadIdx.x] = expf(n2s2 * d * d);
    }
    __syncthreads();

    const float scale = 53.0f / 52.0f;
    float* o = out + (size_t)tile * NPIX;

    for (int pidx = threadIdx.x; pidx < NPIX; pidx += TPB) {
        const int i = pidx / SLEN;          // row  -> y
        const int j = pidx - i * SLEN;      // col  -> x
        const float x = (float)j * scale - 27.0f;
        const float y = (float)i * scale - 27.0f;

        // rotate into SIE frame
        const float dx = x - cx;
        const float dy = y - cy;
        const float xsie = dx * cosp + dy * sinp;
        const float ysie = dy * cosp - dx * sinp;

        // elliptical radius (never zero: +1e-12 under non-negative terms)
        const float t    = fmaf(q * xsie, xsie, fmaf(invq * ysie, ysie, 1e-12f));
        const float rinv = rsqrtf(t);

        float xtg, ytg;
        if (use_t) {
            const float zx = safe * xsie * rinv;
            const float zy = safe * ysie * rinv;               // |zy| <= sqrt(1-q^2) < 1
            xtg = bsafe * atanf(zx);
            const float ratio = __fdividef(1.0f + zy, 1.0f - zy);
            ytg = (bsafe * 0.5f) * __logf(ratio);              // atanh via log
        } else {
            xtg = b * xsie * rinv;
            ytg = b * ysie * rinv;
        }

        // rotate deflection back; sampling coords (image frame, +26 shift)
        const float xg = xtg * cosp - ytg * sinp;
        const float yg = ytg * cosp + xtg * sinp;
        const float xs = x - xg + 26.0f;
        const float ys = y - yg + 26.0f;

        // clamped bilinear indices (exactly the reference's clipping)
        const float fx = floorf(xs);
        const float fy = floorf(ys);
        const int ix = (int)fx;
        const int iy = (int)fy;
        const int x0 = max(0, min(SLEN - 1, ix));
        const int x1 = max(0, min(SLEN - 1, ix + 1));
        const int y0 = max(0, min(SLEN - 1, iy));
        const int y1 = max(0, min(SLEN - 1, iy + 1));

        const float x0f = (float)x0, x1f = (float)x1;
        const float y0f = (float)y0, y1f = (float)y1;

        // separable bilinear of a separable Gaussian:
        // out = Am * (e[x0]*(x1f-xs)+e[x1]*(xs-x0f)) * (e[y0]*(y1f-ys)+e[y1]*(ys-y0f))
        const float wx = etab[x0] * (x1f - xs) + etab[x1] * (xs - x0f);
        const float wy = etab[y0] * (y1f - ys) + etab[y1] * (ys - y0f);

        o[pidx] = Am * wx * wy;
    }
}

extern "C" void kernel_launch(void* const* d_in, const int* in_sizes, int n_in,
                              void* d_out, int out_size)
{
    const float* params = (const float*)d_in[0];   // lens_params  [4096,1,12]
    const float* bmask  = (const float*)d_in[1];   // bools        [4096,1,1]
    float* out = (float*)d_out;

    const int ntiles = out_size / NPIX;            // 4096
    lens_decoder_kernel<<<ntiles, TPB>>>(params, bmask, out);
}

// round 2
// speedup vs baseline: 1.6097x; 1.6097x over previous
#include <cuda_runtime.h>

#define SLEN 53
#define NPIX (SLEN * SLEN)   // 2809
#define TPB  256

__device__ __forceinline__ float frcp_(float x){ float r; asm("rcp.approx.ftz.f32 %0, %1;" : "=f"(r) : "f"(x)); return r; }
__device__ __forceinline__ float flg2_(float x){ float r; asm("lg2.approx.ftz.f32 %0, %1;" : "=f"(r) : "f"(x)); return r; }
__device__ __forceinline__ float frsq_(float x){ float r; asm("rsqrt.approx.ftz.f32 %0, %1;" : "=f"(r) : "f"(x)); return r; }

// Cephes-style atan: two-stage range reduction + degree-7 odd poly.
// Max error ~3e-7 (incl. rcp.approx). Branchless for SIMT.
__device__ __forceinline__ float fast_atan(float v) {
    float a    = fabsf(v);
    float inv  = frcp_(a);            // used when a > tan(3pi/8)
    float invp = frcp_(a + 1.0f);     // used when a > tan(pi/8)
    bool  c1 = a > 2.414213562f;
    bool  c2 = a > 0.414213562f;
    float x  = c1 ? -inv : (c2 ? (a - 1.0f) * invp : a);
    float y0 = c1 ? 1.57079632679f : (c2 ? 0.78539816339f : 0.0f);
    float z = x * x;
    float p = fmaf(8.05374449538e-2f, z, -1.38776856032e-1f);
    p = fmaf(p, z, 1.99777106478e-1f);
    p = fmaf(p, z, -3.33329491539e-1f);
    float y = fmaf(p * z, x, x) + y0;
    return copysignf(y, v);
}

__global__ void __launch_bounds__(TPB, 6)
lens_decoder_kernel(const float* __restrict__ params,   // [ntiles, 12]
                    const float* __restrict__ bools,    // [ntiles]
                    float* __restrict__ out)            // [ntiles, NPIX]
{
    __shared__ float etab[SLEN];

    const int tile = blockIdx.x;
    float* o = out + (size_t)tile * NPIX;
    const float bm = bools[tile];

    // ---- zero-tile fast path (~30% of tiles): output is exactly 0 ----
    if (bm == 0.0f) {
        for (int p = threadIdx.x; p < NPIX; p += TPB) o[p] = 0.0f;
        return;
    }

    // ---- per-tile scalars ----
    const float* pr = params + tile * 12;
    const float flux  = fmaf(pr[0], 1000.0f, 100.0f);
    const float sigma = fmaf(pr[3], 3.0f, 1.0f);
    const float s2    = sigma * sigma;
    const float b     = pr[7];
    const float cx    = pr[8];
    const float cy    = pr[9];
    const float e1p   = pr[10];
    const float e2p   = pr[11];

    const float ell   = sqrtf(e1p * e1p + e2p * e2p);
    const float q     = (1.0f - ell) / (1.0f + ell);
    const float phir  = atanf(e2p / e1p);
    float sinp, cosp;
    sincosf(phir, &sinp, &cosp);
    const float invq  = 1.0f / q;
    // data guarantees q in [0.1, 0.9] -> qfact >= 0.459 >> eps: fallback branch is dead
    const float qfact = sqrtf(invq - q);
    const float bsafe = b / qfact;
    const float Am    = flux / (6.283185307179586f * s2);   // bm == 1 here
    const float sAm   = sqrtf(Am);
    const float n2s2  = -0.5f / s2;
    const float klog  = bsafe * 0.34657359028f;   // bsafe * 0.5 * ln(2)

    // ---- separable Gaussian table, pre-scaled by sqrt(Am) ----
    if (threadIdx.x < SLEN) {
        float d = (float)threadIdx.x - 26.0f;
        etab[threadIdx.x] = sAm * expf(n2s2 * d * d);
    }
    __syncthreads();

    const float scale = 53.0f / 52.0f;

    for (int pidx = threadIdx.x; pidx < NPIX; pidx += TPB) {
        const int i = pidx / SLEN;           // row  -> y
        const int j = pidx - i * SLEN;       // col  -> x
        const float x = fmaf((float)j, scale, -27.0f);
        const float y = fmaf((float)i, scale, -27.0f);

        // rotate into SIE frame
        const float dx = x - cx;
        const float dy = y - cy;
        const float xsie = fmaf(dx, cosp, dy * sinp);
        const float ysie = fmaf(dy, cosp, -dx * sinp);

        // elliptical radius; fold qfact into the reciprocal radius
        const float t     = fmaf(q * xsie, xsie, fmaf(invq * ysie, ysie, 1e-12f));
        const float srinv = qfact * frsq_(t);
        const float zx = xsie * srinv;
        const float zy = ysie * srinv;       // |zy| <= sqrt(1-q^2) <= 0.995

        const float xtg = bsafe * fast_atan(zx);
        const float ratio = (1.0f + zy) * frcp_(1.0f - zy);
        const float ytg = klog * flg2_(ratio);   // bsafe * atanh(zy)

        // rotate deflection back; sampling coords
        const float xs = fmaf(-xtg, cosp, fmaf(ytg, sinp, x + 26.0f));
        const float ys = fmaf(-ytg, cosp, fmaf(-xtg, sinp, y + 26.0f));

        // fractional bilinear (bit-consistent with reference's clamped form,
        // which collapses to exact 0 whenever xs<0 or xs>=52)
        const float fx = floorf(xs);
        const float fy = floorf(ys);
        const float ffx = xs - fx;
        const float ffy = ys - fy;
        const int ix = (int)fx;
        const int iy = (int)fy;
        const int icx = min(max(ix, 0), SLEN - 2);
        const int icy = min(max(iy, 0), SLEN - 2);

        const float ex0 = etab[icx], ex1 = etab[icx + 1];
        const float ey0 = etab[icy], ey1 = etab[icy + 1];

        const float wx = ((unsigned)ix < (unsigned)(SLEN - 1)) ? fmaf(ffx, ex1 - ex0, ex0) : 0.0f;
        const float wy = ((unsigned)iy < (unsigned)(SLEN - 1)) ? fmaf(ffy, ey1 - ey0, ey0) : 0.0f;

        o[pidx] = wx * wy;
    }
}

extern "C" void kernel_launch(void* const* d_in, const int* in_sizes, int n_in,
                              void* d_out, int out_size)
{
    const float* params = (const float*)d_in[0];   // lens_params  [4096,1,12]
    const float* bmask  = (const float*)d_in[1];   // bools        [4096,1,1]
    float* out = (float*)d_out;

    const int ntiles = out_size / NPIX;            // 4096
    lens_decoder_kernel<<<ntiles, TPB>>>(params, bmask, out);
}

// round 3
// speedup vs baseline: 1.7162x; 1.0661x over previous
#include <cuda_runtime.h>

#define SLEN   53
#define NPIX   (SLEN * SLEN)     // 2809
#define TPB    256
#define NQUADS (SLEN * 14)       // 742: 14 x-quads per row

__device__ __forceinline__ float frcp_(float x){ float r; asm("rcp.approx.ftz.f32 %0, %1;" : "=f"(r) : "f"(x)); return r; }
__device__ __forceinline__ float flg2_(float x){ float r; asm("lg2.approx.ftz.f32 %0, %1;" : "=f"(r) : "f"(x)); return r; }
__device__ __forceinline__ float frsq_(float x){ float r; asm("rsqrt.approx.ftz.f32 %0, %1;" : "=f"(r) : "f"(x)); return r; }

// Cephes-style atan, single-MUFU variant: select numerator/denominator
// BEFORE the reciprocal so only one rcp is issued. Max err ~3e-7.
__device__ __forceinline__ float fast_atan(float v) {
    float a  = fabsf(v);
    bool  c1 = a > 2.414213562f;     // > tan(3pi/8): x = -1/a
    bool  c2 = a > 0.414213562f;     // > tan(pi/8):  x = (a-1)/(a+1)
    float num = c1 ? -1.0f : (a - 1.0f);
    float den = c1 ?  a    : (a + 1.0f);
    float xr  = num * frcp_(den);
    float x   = c2 ? xr : a;
    float y0  = c1 ? 1.57079632679f : (c2 ? 0.78539816339f : 0.0f);
    float z = x * x;
    float p = fmaf(8.05374449538e-2f, z, -1.38776856032e-1f);
    p = fmaf(p, z, 1.99777106478e-1f);
    p = fmaf(p, z, -3.33329491539e-1f);
    float y = fmaf(p * z, x, x) + y0;
    return copysignf(y, v);
}

__global__ void __launch_bounds__(TPB)
lens_decoder_kernel(const float* __restrict__ params,   // [ntiles, 12]
                    const float* __restrict__ bools,    // [ntiles]
                    float* __restrict__ out)            // [ntiles, NPIX]
{
    __shared__ float2 etab[SLEN];    // (e[k], e[k+1]-e[k])

    const int tile = blockIdx.x;
    float* o = out + (size_t)tile * NPIX;
    const float bm = bools[tile];

    // ---- zero-tile fast path (~30% of tiles) ----
    if (bm == 0.0f) {
        for (int p = threadIdx.x; p < NPIX; p += TPB) o[p] = 0.0f;
        return;
    }

    // ---- per-tile scalars ----
    const float* pr = params + tile * 12;
    const float flux  = fmaf(pr[0], 1000.0f, 100.0f);
    const float sigma = fmaf(pr[3], 3.0f, 1.0f);
    const float s2    = sigma * sigma;
    const float b     = pr[7];
    const float cx    = pr[8];
    const float cy    = pr[9];
    const float e1p   = pr[10];
    const float e2p   = pr[11];

    const float ell   = sqrtf(e1p * e1p + e2p * e2p);
    const float q     = (1.0f - ell) / (1.0f + ell);
    const float phir  = atanf(e2p / e1p);
    float sinp, cosp;
    sincosf(phir, &sinp, &cosp);
    const float invq  = 1.0f / q;
    // data guarantees q in [0.1, 0.9] -> qfact >= 0.459 >> eps (fallback dead)
    const float qfact = sqrtf(invq - q);
    const float bsafe = b / qfact;
    const float sAm   = sqrtf(flux / (6.283185307179586f * s2));
    const float n2s2  = -0.5f / s2;
    const float klog  = bsafe * 0.34657359028f;   // bsafe * 0.5 * ln2

    // ---- separable Gaussian table, pre-scaled by sqrt(Am), with deltas ----
    __shared__ float etmp[SLEN + 1];
    if (threadIdx.x < SLEN) {
        float d = (float)threadIdx.x - 26.0f;
        etmp[threadIdx.x] = sAm * expf(n2s2 * d * d);
        if (threadIdx.x == 0) etmp[SLEN] = 0.0f;   // never read (icx<=51)
    }
    __syncthreads();
    if (threadIdx.x < SLEN) {
        float e0 = etmp[threadIdx.x];
        float e1 = etmp[threadIdx.x + 1];
        etab[threadIdx.x] = make_float2(e0, e1 - e0);
    }
    __syncthreads();

    const float scale = 53.0f / 52.0f;
    const float dxsie = scale * cosp;      // per-x-step increments in SIE frame
    const float dysie = -scale * sinp;

    for (int qi = threadIdx.x; qi < NQUADS; qi += TPB) {
        const int i  = qi / 14;            // row (y)
        const int jq = qi - i * 14;
        const int j0 = jq * 4;             // first x of quad

        const float yc = fmaf((float)i,  scale, -1.0f);   // y + 26
        const float dy = yc - (cy + 26.0f);               // y - cy
        const float xc0 = fmaf((float)j0, scale, -1.0f);  // x + 26
        const float dx0 = xc0 - (cx + 26.0f);             // x - cx

        float xsie = fmaf(dx0, cosp,  dy * sinp);
        float ysie = fmaf(dy,  cosp, -dx0 * sinp);
        float xc   = xc0;

        float* orow = o + i * SLEN + j0;

        #pragma unroll
        for (int k = 0; k < 4; k++) {
            if (j0 + k < SLEN) {
                const float t     = fmaf(q * xsie, xsie, fmaf(invq * ysie, ysie, 1e-12f));
                const float srinv = qfact * frsq_(t);
                const float zx = xsie * srinv;
                const float zy = ysie * srinv;            // |zy| <= 0.995

                const float xtg = bsafe * fast_atan(zx);
                const float ratio = (1.0f + zy) * frcp_(1.0f - zy);
                const float ytg = klog * flg2_(ratio);    // bsafe * atanh(zy)

                // sampling coords (image frame, +26 already in xc/yc)
                const float xs = fmaf(-xtg, cosp, fmaf( ytg, sinp, xc));
                const float ys = fmaf(-ytg, cosp, fmaf(-xtg, sinp, yc));

                const float fx = floorf(xs);
                const float fy = floorf(ys);
                const float ffx = xs - fx;
                const float ffy = ys - fy;
                const int ix = (int)fx;
                const int iy = (int)fy;
                const int icx = min(max(ix, 0), SLEN - 2);
                const int icy = min(max(iy, 0), SLEN - 2);

                const float2 exd = etab[icx];
                const float2 eyd = etab[icy];

                const float wx = ((unsigned)ix < (unsigned)(SLEN - 1)) ? fmaf(ffx, exd.y, exd.x) : 0.0f;
                const float wy = ((unsigned)iy < (unsigned)(SLEN - 1)) ? fmaf(ffy, eyd.y, eyd.x) : 0.0f;

                orow[k] = wx * wy;
            }
            xsie += dxsie;
            ysie += dysie;
            xc   += scale;
        }
    }
}

extern "C" void kernel_launch(void* const* d_in, const int* in_sizes, int n_in,
                              void* d_out, int out_size)
{
    const float* params = (const float*)d_in[0];   // lens_params  [4096,1,12]
    const float* bmask  = (const float*)d_in[1];   // bools        [4096,1,1]
    float* out = (float*)d_out;

    const int ntiles = out_size / NPIX;            // 4096
    lens_decoder_kernel<<<ntiles, TPB>>>(params, bmask, out);
}

// round 4
// speedup vs baseline: 1.8498x; 1.0779x over previous
#include <cuda_runtime.h>

#define SLEN   53
#define NPIX   (SLEN * SLEN)     // 2809
#define TPB    256
#define NSTRIP 14                // ceil(53/4) row-strips
#define NUNITS (SLEN * NSTRIP)   // 742 work units (column x row-strip)

__device__ __forceinline__ float frcp_(float x){ float r; asm("rcp.approx.ftz.f32 %0, %1;" : "=f"(r) : "f"(x)); return r; }
__device__ __forceinline__ float flg2_(float x){ float r; asm("lg2.approx.ftz.f32 %0, %1;" : "=f"(r) : "f"(x)); return r; }
__device__ __forceinline__ float frsq_(float x){ float r; asm("rsqrt.approx.ftz.f32 %0, %1;" : "=f"(r) : "f"(x)); return r; }

// Cephes-style atan, single MUFU rcp. Max err ~3e-7.
__device__ __forceinline__ float fast_atan(float v) {
    float a  = fabsf(v);
    bool  c1 = a > 2.414213562f;
    bool  c2 = a > 0.414213562f;
    float num = c1 ? -1.0f : (a - 1.0f);
    float den = c1 ?  a    : (a + 1.0f);
    float xr  = num * frcp_(den);
    float x   = c2 ? xr : a;
    float y0  = c1 ? 1.57079632679f : (c2 ? 0.78539816339f : 0.0f);
    float z = x * x;
    float p = fmaf(8.05374449538e-2f, z, -1.38776856032e-1f);
    p = fmaf(p, z, 1.99777106478e-1f);
    p = fmaf(p, z, -3.33329491539e-1f);
    float y = fmaf(p * z, x, x) + y0;
    return copysignf(y, v);
}

__global__ void __launch_bounds__(TPB)
lens_decoder_kernel(const float* __restrict__ params,   // [ntiles, 12]
                    const float* __restrict__ bools,    // [ntiles]
                    float* __restrict__ out)            // [ntiles, NPIX]
{
    // sentinel table: etab[0] and etab[53] are zero rows.
    // etab[k+1] = (e[k], e[k+1]-e[k]) for k in [0,51]; etab[53]=(0,0) covers ix=52.
    __shared__ float2 etab[SLEN + 1];
    __shared__ float  etmp[SLEN];

    const int tile = blockIdx.x;
    float* o = out + (size_t)tile * NPIX;
    const float bm = bools[tile];

    // ---- zero-tile fast path (~30% of tiles): exact 0 output ----
    if (bm == 0.0f) {
        for (int p = threadIdx.x; p < NPIX; p += TPB) o[p] = 0.0f;
        return;
    }

    // ---- per-tile scalars ----
    const float* pr = params + tile * 12;
    const float flux  = fmaf(pr[0], 1000.0f, 100.0f);
    const float sigma = fmaf(pr[3], 3.0f, 1.0f);
    const float s2    = sigma * sigma;
    const float b     = pr[7];
    const float cx    = pr[8];
    const float cy    = pr[9];
    const float e1p   = pr[10];
    const float e2p   = pr[11];

    const float ell   = sqrtf(e1p * e1p + e2p * e2p);
    const float q     = (1.0f - ell) / (1.0f + ell);
    const float phir  = atanf(e2p / e1p);
    float sinp, cosp;
    sincosf(phir, &sinp, &cosp);
    const float invq  = 1.0f / q;
    // data guarantees q in [0.1, 0.9] -> qfact >= 0.459 >> eps (fallback dead)
    const float qfact = sqrtf(invq - q);
    const float bsafe = b / qfact;
    const float sAm   = sqrtf(flux / (6.283185307179586f * s2));
    const float n2s2  = -0.5f / s2;
    const float klog  = bsafe * 0.34657359028f;   // bsafe * 0.5 * ln2

    // ---- pre-scaled separable Gaussian table with deltas + zero sentinels ----
    if (threadIdx.x < SLEN) {
        float d = (float)threadIdx.x - 26.0f;
        etmp[threadIdx.x] = sAm * expf(n2s2 * d * d);
    }
    __syncthreads();
    if (threadIdx.x < SLEN + 1) {
        int t = threadIdx.x;
        if (t == 0 || t == SLEN) {
            etab[t] = make_float2(0.0f, 0.0f);
        } else {
            float e0 = etmp[t - 1];
            float e1 = etmp[t];          // t-1 in [0,51] -> t in [1,52]
            etab[t] = make_float2(e0, e1 - e0);
        }
    }
    __syncthreads();

    const float scale = 53.0f / 52.0f;
    const float dxs_y = scale * sinp;     // d(xsie)/d(row)
    const float dys_y = scale * cosp;     // d(ysie)/d(row)

    for (int u = threadIdx.x; u < NUNITS; u += TPB) {
        const int strip = u / SLEN;       // row strip (4 rows)
        const int j     = u - strip * SLEN;
        const int i0    = strip * 4;

        const float xc  = fmaf((float)j,  scale, -1.0f);  // x + 26 (constant in strip)
        const float yc0 = fmaf((float)i0, scale, -1.0f);  // y + 26 at first row
        const float dx  = xc  - (cx + 26.0f);
        const float dy0 = yc0 - (cy + 26.0f);

        float xsie = fmaf(dx,  cosp,  dy0 * sinp);
        float ysie = fmaf(dy0, cosp, -dx  * sinp);
        float yc   = yc0;

        float* ocol = o + i0 * SLEN + j;

        #pragma unroll
        for (int k = 0; k < 4; k++) {
            if (i0 + k < SLEN) {
                const float t     = fmaf(q * xsie, xsie, fmaf(invq * ysie, ysie, 1e-12f));
                const float srinv = qfact * frsq_(t);
                const float zx = xsie * srinv;
                const float zy = ysie * srinv;            // |zy| <= 0.995

                const float xtg = bsafe * fast_atan(zx);
                const float ratio = (1.0f + zy) * frcp_(1.0f - zy);
                const float ytg = klog * flg2_(ratio);    // bsafe * atanh(zy)

                const float xs = fmaf(-xtg, cosp, fmaf( ytg, sinp, xc));
                const float ys = fmaf(-ytg, cosp, fmaf(-xtg, sinp, yc));

                const float fx = floorf(xs);
                const float fy = floorf(ys);
                const float ffx = xs - fx;
                const float ffy = ys - fy;
                const int idx = min(max((int)fx, -1), SLEN - 1) + 1;  // [0,53]
                const int idy = min(max((int)fy, -1), SLEN - 1) + 1;

                const float2 exd = etab[idx];
                const float2 eyd = etab[idy];

                const float wx = fmaf(ffx, exd.y, exd.x);
                const float wy = fmaf(ffy, eyd.y, eyd.x);

                ocol[k * SLEN] = wx * wy;   // coalesced: lanes -> consecutive j
            }
            xsie += dxs_y;
            ysie += dys_y;
            yc   += scale;
        }
    }
}

extern "C" void kernel_launch(void* const* d_in, const int* in_sizes, int n_in,
                              void* d_out, int out_size)
{
    const float* params = (const float*)d_in[0];   // lens_params  [4096,1,12]
    const float* bmask  = (const float*)d_in[1];   // bools        [4096,1,1]
    float* out = (float*)d_out;

    const int ntiles = out_size / NPIX;            // 4096
    lens_decoder_kernel<<<ntiles, TPB>>>(params, bmask, out);
}

// round 5
// speedup vs baseline: 1.9941x; 1.0780x over previous
#include <cuda_runtime.h>

#define SLEN   53
#define NPIX   (SLEN * SLEN)     // 2809
#define TPB    256
#define NMAIN  (SLEN * 13)       // 689 four-row units (rows 0..51)

__device__ __forceinline__ float frcp_(float x){ float r; asm("rcp.approx.ftz.f32 %0, %1;" : "=f"(r) : "f"(x)); return r; }
__device__ __forceinline__ float flg2_(float x){ float r; asm("lg2.approx.ftz.f32 %0, %1;" : "=f"(r) : "f"(x)); return r; }
__device__ __forceinline__ float frsq_(float x){ float r; asm("rsqrt.approx.ftz.f32 %0, %1;" : "=f"(r) : "f"(x)); return r; }

// Cephes-style atan, single MUFU rcp. Max err ~3e-7.
__device__ __forceinline__ float fast_atan(float v) {
    float a  = fabsf(v);
    bool  c1 = a > 2.414213562f;
    bool  c2 = a > 0.414213562f;
    float num = c1 ? -1.0f : (a - 1.0f);
    float den = c1 ?  a    : (a + 1.0f);
    float xr  = num * frcp_(den);
    float x   = c2 ? xr : a;
    float y0  = c1 ? 1.57079632679f : (c2 ? 0.78539816339f : 0.0f);
    float z = x * x;
    float p = fmaf(8.05374449538e-2f, z, -1.38776856032e-1f);
    p = fmaf(p, z, 1.99777106478e-1f);
    p = fmaf(p, z, -3.33329491539e-1f);
    float y = fmaf(p * z, x, x) + y0;
    return copysignf(y, v);
}

// smem scalar slots
#define S_Q     0
#define S_INVQ  1
#define S_QF    2
#define S_BSAFE 3
#define S_KLOG  4
#define S_COSP  5
#define S_SINP  6
#define S_CX26  7
#define S_CY26  8
#define S_SAM   9
#define S_N2S2  10

__global__ void __launch_bounds__(TPB)
lens_decoder_kernel(const float* __restrict__ params,   // [ntiles, 12]
                    const float* __restrict__ bools,    // [ntiles]
                    float* __restrict__ out)            // [ntiles, NPIX]
{
    __shared__ float  sc[12];
    __shared__ float  etmp[SLEN];
    __shared__ float2 etab[SLEN + 1];   // zero sentinels at [0] and [53]

    const int tid  = threadIdx.x;
    const int tile = blockIdx.x;
    float* o = out + (size_t)tile * NPIX;

    // ---- zero-tile fast path (~30% of tiles): exact 0 output ----
    if (bools[tile] == 0.0f) {
        for (int p = tid; p < NPIX; p += TPB) o[p] = 0.0f;
        return;
    }

    // ---- per-tile scalars: computed ONCE by thread 0, broadcast via smem ----
    if (tid == 0) {
        const float* pr = params + tile * 12;
        const float flux  = fmaf(pr[0], 1000.0f, 100.0f);
        const float sigma = fmaf(pr[3], 3.0f, 1.0f);
        const float s2    = sigma * sigma;
        const float b     = pr[7];
        const float e1p   = pr[10];
        const float e2p   = pr[11];

        const float ell   = sqrtf(e1p * e1p + e2p * e2p);
        const float q     = (1.0f - ell) / (1.0f + ell);
        const float phir  = atanf(e2p / e1p);
        float sinp, cosp;
        sincosf(phir, &sinp, &cosp);
        const float invq  = 1.0f / q;
        // data guarantees q in [0.1, 0.9] -> qfact >= 0.459 >> eps (fallback dead)
        const float qfact = sqrtf(invq - q);
        const float bsafe = b / qfact;

        sc[S_Q]     = q;
        sc[S_INVQ]  = invq;
        sc[S_QF]    = qfact;
        sc[S_BSAFE] = bsafe;
        sc[S_KLOG]  = bsafe * 0.34657359028f;   // bsafe * 0.5 * ln2
        sc[S_COSP]  = cosp;
        sc[S_SINP]  = sinp;
        sc[S_CX26]  = pr[8] + 26.0f;
        sc[S_CY26]  = pr[9] + 26.0f;
        sc[S_SAM]   = sqrtf(flux / (6.283185307179586f * s2));
        sc[S_N2S2]  = -0.5f / s2;
    }
    __syncthreads();

    // ---- pre-scaled separable Gaussian table with deltas + zero sentinels ----
    if (tid < SLEN) {
        float d = (float)tid - 26.0f;
        etmp[tid] = sc[S_SAM] * expf(sc[S_N2S2] * d * d);
    }
    __syncthreads();
    if (tid < SLEN + 1) {
        if (tid == 0 || tid == SLEN) {
            etab[tid] = make_float2(0.0f, 0.0f);
        } else {
            float e0 = etmp[tid - 1];
            float e1 = etmp[tid];
            etab[tid] = make_float2(e0, e1 - e0);
        }
    }
    __syncthreads();

    // broadcast scalar loads (LDS, conflict-free)
    const float q     = sc[S_Q];
    const float invq  = sc[S_INVQ];
    const float qfact = sc[S_QF];
    const float bsafe = sc[S_BSAFE];
    const float klog  = sc[S_KLOG];
    const float cosp  = sc[S_COSP];
    const float sinp  = sc[S_SINP];
    const float cx26  = sc[S_CX26];
    const float cy26  = sc[S_CY26];

    const float scale = 53.0f / 52.0f;
    const float dxs_y = scale * sinp;     // d(xsie)/d(row)
    const float dys_y = scale * cosp;     // d(ysie)/d(row)

    // one-pixel body: coords (xsie, ysie), image coords (xc = x+26, yc = y+26)
    auto pixel = [&](float xsie, float ysie, float xc, float yc) -> float {
        const float t     = fmaf(q * xsie, xsie, fmaf(invq * ysie, ysie, 1e-12f));
        const float srinv = qfact * frsq_(t);
        const float zx = xsie * srinv;
        const float zy = ysie * srinv;            // |zy| <= 0.995

        const float xtg = bsafe * fast_atan(zx);
        const float ratio = (1.0f + zy) * frcp_(1.0f - zy);
        const float ytg = klog * flg2_(ratio);    // bsafe * atanh(zy)

        const float xs = fmaf(-xtg, cosp, fmaf( ytg, sinp, xc));
        const float ys = fmaf(-ytg, cosp, fmaf(-xtg, sinp, yc));

        const float fx = floorf(xs);
        const float fy = floorf(ys);
        const float ffx = xs - fx;
        const float ffy = ys - fy;
        // float-domain clamp to [-1, 52], then +1 -> [0, 53]
        const int idx = (int)fminf(fmaxf(fx, -1.0f), 52.0f) + 1;
        const int idy = (int)fminf(fmaxf(fy, -1.0f), 52.0f) + 1;

        const float2 exd = etab[idx];
        const float2 eyd = etab[idy];
        const float wx = fmaf(ffx, exd.y, exd.x);
        const float wy = fmaf(ffy, eyd.y, eyd.x);
        return wx * wy;
    };

    // ---- main: 689 four-row units (rows 0..51), no per-pixel bounds check ----
    for (int u = tid; u < NMAIN; u += TPB) {
        const int strip = (u * 1237) >> 16;        // == u/53 for u < 742
        const int j     = u - strip * 53;
        const int i0    = strip * 4;

        const float xc  = fmaf((float)j,  scale, -1.0f);  // x + 26
        const float yc0 = fmaf((float)i0, scale, -1.0f);  // y + 26
        const float dx  = xc  - cx26;
        const float dy0 = yc0 - cy26;

        float xsie = fmaf(dx,  cosp,  dy0 * sinp);
        float ysie = fmaf(dy0, cosp, -dx  * sinp);
        float yc   = yc0;

        float* ocol = o + i0 * SLEN + j;

        #pragma unroll
        for (int k = 0; k < 4; k++) {
            ocol[k * SLEN] = pixel(xsie, ysie, xc, yc);
            xsie += dxs_y;
            ysie += dys_y;
            yc   += scale;
        }
    }

    // ---- tail: row 52, one pixel per thread ----
    if (tid < SLEN) {
        const int j = tid;
        const float xc = fmaf((float)j, scale, -1.0f);
        const float yc = fmaf(52.0f, scale, -1.0f);
        const float dx = xc - cx26;
        const float dy = yc - cy26;
        const float xsie = fmaf(dx, cosp,  dy * sinp);
        const float ysie = fmaf(dy, cosp, -dx * sinp);
        o[52 * SLEN + j] = pixel(xsie, ysie, xc, yc);
    }
}

extern "C" void kernel_launch(void* const* d_in, const int* in_sizes, int n_in,
                              void* d_out, int out_size)
{
    const float* params = (const float*)d_in[0];   // lens_params  [4096,1,12]
    const float* bmask  = (const float*)d_in[1];   // bools        [4096,1,1]
    float* out = (float*)d_out;

    const int ntiles = out_size / NPIX;            // 4096
    lens_decoder_kernel<<<ntiles, TPB>>>(params, bmask, out);
}